// round 6
// baseline (speedup 1.0000x reference)
#include <cuda_runtime.h>

// LUT-tree conv: B=8, C=64, H=W=32, O=32, Q=8, K=3.
// R5: Möbius-transformed LUT coeffs (pure-FMA Horner, no FADD),
//     packed fma.rn.f32x2 over pixel pairs (2 px / instruction),
//     H split in half (grid 512 x 128thr) for occupancy,
//     vectorized feature row loads (float4+float2), stride 36.

#define STRIDE 36
#define PLANE  (18 * STRIDE)          // 648 floats per channel plane (18 rows incl halo)
typedef unsigned long long ull;

#define HPACK 0x3F0000003F000000ULL   // (0.5f, 0.5f)

__device__ __forceinline__ float fsig(float x) {
    // sigmoid via ex2.approx + rcp.approx (~1e-6 rel err, 2 MUFU)
    float e, r;
    asm("ex2.approx.f32 %0, %1;" : "=f"(e) : "f"(x * -1.4426950408889634f));
    asm("rcp.approx.f32 %0, %1;" : "=f"(r) : "f"(1.0f + e));
    return r;
}

__device__ __forceinline__ ull pk(float a, float b) {
    ull d;
    asm("mov.b64 %0, {%1, %2};"
        : "=l"(d) : "r"(__float_as_uint(a)), "r"(__float_as_uint(b)));
    return d;
}
__device__ __forceinline__ void upk(ull v, float& a, float& b) {
    unsigned lo, hi;
    asm("mov.b64 {%0, %1}, %2;" : "=r"(lo), "=r"(hi) : "l"(v));
    a = __uint_as_float(lo); b = __uint_as_float(hi);
}
__device__ __forceinline__ ull fma2(ull a, ull b, ull c) {
    // packed f32x2 fma: 2 pixels per instruction (Blackwell)
    ull d;
    asm("fma.rn.f32x2 %0, %1, %2, %3;" : "=l"(d) : "l"(a), "l"(b), "l"(c));
    return d;
}
__device__ __forceinline__ ull sigp(ull v) {
    float a, b; upk(v, a, b);
    return pk(fsig(a), fsig(b));
}

// Horner eval of multilinear poly with Möbius-transformed coeffs:
// 15 packed FMAs, zero subtracts. Bit i of coeff index == input i.
__device__ __forceinline__ ull lut4p(const ull c[16], ull x0, ull x1, ull x2, ull x3) {
    ull u0 = fma2(x0, c[1],  c[0]);
    ull u1 = fma2(x0, c[3],  c[2]);
    ull u2 = fma2(x0, c[5],  c[4]);
    ull u3 = fma2(x0, c[7],  c[6]);
    ull u4 = fma2(x0, c[9],  c[8]);
    ull u5 = fma2(x0, c[11], c[10]);
    ull u6 = fma2(x0, c[13], c[12]);
    ull u7 = fma2(x0, c[15], c[14]);
    ull v0 = fma2(x1, u1, u0);
    ull v1 = fma2(x1, u3, u2);
    ull v2 = fma2(x1, u5, u4);
    ull v3 = fma2(x1, u7, u6);
    ull w0 = fma2(x2, v1, v0);
    ull w1 = fma2(x2, v3, v2);
    return fma2(x3, w1, w0);
}

// Load 16 duplicated-packed coeffs for LUT `lut` (uniform -> LDS.128 broadcast).
__device__ __forceinline__ void ldc16(ull c[16], const float* Wc, int lut) {
    const ulonglong2* p = reinterpret_cast<const ulonglong2*>(Wc + lut * 32);
    #pragma unroll
    for (int j = 0; j < 8; j++) {
        ulonglong2 t = p[j];
        c[2 * j] = t.x; c[2 * j + 1] = t.y;
    }
}

__global__ __launch_bounds__(128, 4) void lut_tree_kernel(
    const float* __restrict__ x,
    const float* __restrict__ w0, const float* __restrict__ w1,
    const float* __restrict__ w2, const float* __restrict__ w3,
    const int* __restrict__ ci, float* __restrict__ out)
{
    __shared__ __align__(16) float S[8 * PLANE];   // sigmoided channels + halo
    __shared__ __align__(16) float Wc[26 * 32];    // Möbius coeffs, duplicated pairs

    const int o   = blockIdx.x;          // 0..31
    const int b   = blockIdx.y;          // 0..7
    const int h0  = blockIdx.z << 4;     // 0 or 16
    const int tid = threadIdx.x;

    // ---- Stage + Möbius-transform weights (thread t handles LUT t) ----
    if (tid < 26) {
        const float* src;
        if (tid < 18)      src = w0 + o * 288 + tid * 16;
        else if (tid < 23) src = w1 + o * 80  + (tid - 18) * 16;
        else if (tid < 25) src = w2 + o * 32  + (tid - 23) * 16;
        else               src = w3 + o * 16;
        float t16[16];
        #pragma unroll
        for (int i = 0; i < 16; i++) t16[i] = src[i];
        // full finite-difference (Möbius) transform along all 4 dims
        #pragma unroll
        for (int d = 0; d < 4; d++) {
            const int s = 1 << d;
            #pragma unroll
            for (int j = 0; j < 16; j++)
                if (j & s) t16[j] -= t16[j ^ s];
        }
        #pragma unroll
        for (int i = 0; i < 16; i++) {
            Wc[tid * 32 + 2 * i]     = t16[i];
            Wc[tid * 32 + 2 * i + 1] = t16[i];
        }
    }

    // ---- Init planes to sigmoid(0)=0.5 (covers conv zero-pad halo) ----
    for (int i = tid; i < 8 * PLANE; i += 128) S[i] = 0.5f;
    __syncthreads();

    // ---- Fill interior: sigmoid of selected channels for this h-half ----
    #pragma unroll
    for (int q = 0; q < 8; q++) {
        const int ch = ci[o * 8 + q];
        const float* xc = x + ((size_t)(b * 64 + ch)) * 1024;
        for (int i = tid; i < 18 * 32; i += 128) {
            const int r = i >> 5, w = i & 31;
            const int hin = h0 - 1 + r;
            if (hin >= 0 && hin < 32)
                S[q * PLANE + r * STRIDE + 1 + w] = fsig(xc[hin * 32 + w]);
        }
    }
    __syncthreads();

    // ---- Eval: thread -> output row ty (of 16), 4 cols = 2 pixel pairs ----
    const int ty = tid >> 3;          // 0..15
    const int wb = (tid & 7) << 2;    // 0..28

    ull h1A[5], h1B[5];               // sigmoided level-1 outputs (pairs A=(p0,p1), B=(p2,p3))

    #pragma unroll
    for (int g = 0; g < 5; g++) {
        ull inA[4], inB[4];
        #pragma unroll
        for (int k = 0; k < 4; k++) {
            const int l = g * 4 + k;
            if (l < 18) {
                ull c[16]; ldc16(c, Wc, l);
                // features j=4l..4l+3 span exactly 2 feature-rows rA, rA+1
                const int rA = (4 * l) / 3;
                const int rB = rA + 1;
                float va[6], vb[6];
                {
                    const float* pa = S + (rA / 3) * PLANE + (ty + rA % 3) * STRIDE + wb;
                    float4 f = *(const float4*)pa;
                    float2 g2 = *(const float2*)(pa + 4);
                    va[0]=f.x; va[1]=f.y; va[2]=f.z; va[3]=f.w; va[4]=g2.x; va[5]=g2.y;
                }
                {
                    const float* pb = S + (rB / 3) * PLANE + (ty + rB % 3) * STRIDE + wb;
                    float4 f = *(const float4*)pb;
                    float2 g2 = *(const float2*)(pb + 4);
                    vb[0]=f.x; vb[1]=f.y; vb[2]=f.z; vb[3]=f.w; vb[4]=g2.x; vb[5]=g2.y;
                }
                ull xA[4], xB[4];
                #pragma unroll
                for (int i = 0; i < 4; i++) {
                    const int j  = 4 * l + i;
                    const int rr = j / 3;
                    const int kw = j % 3;
                    const float e0 = (rr == rA) ? va[kw]     : vb[kw];
                    const float e1 = (rr == rA) ? va[kw + 1] : vb[kw + 1];
                    const float e2 = (rr == rA) ? va[kw + 2] : vb[kw + 2];
                    const float e3 = (rr == rA) ? va[kw + 3] : vb[kw + 3];
                    xA[i] = pk(e0, e1);
                    xB[i] = pk(e2, e3);
                }
                inA[k] = sigp(lut4p(c, xA[0], xA[1], xA[2], xA[3]));
                inB[k] = sigp(lut4p(c, xB[0], xB[1], xB[2], xB[3]));
            } else {
                inA[k] = HPACK; inB[k] = HPACK;   // post-sigmoid pad = 0.5
            }
        }
        ull c[16]; ldc16(c, Wc, 18 + g);
        h1A[g] = sigp(lut4p(c, inA[0], inA[1], inA[2], inA[3]));
        h1B[g] = sigp(lut4p(c, inB[0], inB[1], inB[2], inB[3]));
    }

    // Level 2
    ull h2A0, h2B0, h2A1, h2B1;
    {
        ull c[16]; ldc16(c, Wc, 23);
        h2A0 = sigp(lut4p(c, h1A[0], h1A[1], h1A[2], h1A[3]));
        h2B0 = sigp(lut4p(c, h1B[0], h1B[1], h1B[2], h1B[3]));
    }
    {
        ull c[16]; ldc16(c, Wc, 24);
        h2A1 = sigp(lut4p(c, h1A[4], HPACK, HPACK, HPACK));
        h2B1 = sigp(lut4p(c, h1B[4], HPACK, HPACK, HPACK));
    }

    // Level 3 (no sigmoid)
    ull rA, rB;
    {
        ull c[16]; ldc16(c, Wc, 25);
        rA = lut4p(c, h2A0, h2A1, HPACK, HPACK);
        rB = lut4p(c, h2B0, h2B1, HPACK, HPACK);
    }

    float r0, r1, r2, r3;
    upk(rA, r0, r1);
    upk(rB, r2, r3);

    const int h = h0 + ty;
    *reinterpret_cast<float4*>(&out[(((b * 32 + o) * 32 + h) * 32) + wb]) =
        make_float4(r0, r1, r2, r3);
}

extern "C" void kernel_launch(void* const* d_in, const int* in_sizes, int n_in,
                              void* d_out, int out_size) {
    const float* x  = (const float*)d_in[0];
    const float* w0 = (const float*)d_in[1];
    const float* w1 = (const float*)d_in[2];
    const float* w2 = (const float*)d_in[3];
    const float* w3 = (const float*)d_in[4];
    const int*   ci = (const int*)d_in[5];
    dim3 grid(32, 8, 2);   // (O, B, H-half)
    lut_tree_kernel<<<grid, 128>>>(x, w0, w1, w2, w3, ci, (float*)d_out);
}

// round 7
// speedup vs baseline: 1.2003x; 1.2003x over previous
#include <cuda_runtime.h>

// LUT-tree conv: B=8, C=64, H=W=32, O=32, Q=8, K=3.
// R6: scalar Möbius-Horner LUT4 (15 FMA, no FADD, no f32x2 packing),
//     2 px/thread + quarter-H blocks -> 4096 warps (2x R4/R5) for latency hiding,
//     float4-broadcast coeff loads, float2 feature loads, stride 36.

#define STRIDE 36
#define HROWS  10                    // 8 output rows + 2 halo
#define PLANE  (HROWS * STRIDE)     // 360 floats per channel plane

__device__ __forceinline__ float fsig(float x) {
    // sigmoid via ex2.approx + rcp.approx (~1e-6 rel err, 2 MUFU)
    float e, r;
    asm("ex2.approx.f32 %0, %1;" : "=f"(e) : "f"(x * -1.4426950408889634f));
    asm("rcp.approx.f32 %0, %1;" : "=f"(r) : "f"(1.0f + e));
    return r;
}

// Horner eval of the multilinear interp with Möbius (finite-difference)
// transformed coeffs: 15 FMA, zero FADD. Bit i of coeff index == input i.
__device__ __forceinline__ float lut4m(const float c[16],
                                       float x0, float x1, float x2, float x3) {
    float u0 = fmaf(x0, c[1],  c[0]);
    float u1 = fmaf(x0, c[3],  c[2]);
    float u2 = fmaf(x0, c[5],  c[4]);
    float u3 = fmaf(x0, c[7],  c[6]);
    float u4 = fmaf(x0, c[9],  c[8]);
    float u5 = fmaf(x0, c[11], c[10]);
    float u6 = fmaf(x0, c[13], c[12]);
    float u7 = fmaf(x0, c[15], c[14]);
    float v0 = fmaf(x1, u1, u0);
    float v1 = fmaf(x1, u3, u2);
    float v2 = fmaf(x1, u5, u4);
    float v3 = fmaf(x1, u7, u6);
    float w0 = fmaf(x2, v1, v0);
    float w1 = fmaf(x2, v3, v2);
    return fmaf(x3, w1, w0);
}

// Coeff fetch: 4x LDS.128 broadcast (uniform address -> 1 crossbar cyc each).
__device__ __forceinline__ void ldc16(float c[16], const float* Wc, int lut) {
    const float4* p = reinterpret_cast<const float4*>(Wc + lut * 16);
    #pragma unroll
    for (int j = 0; j < 4; j++) {
        float4 t = p[j];
        c[4*j+0] = t.x; c[4*j+1] = t.y; c[4*j+2] = t.z; c[4*j+3] = t.w;
    }
}

__global__ __launch_bounds__(128, 6) void lut_tree_kernel(
    const float* __restrict__ x,
    const float* __restrict__ w0, const float* __restrict__ w1,
    const float* __restrict__ w2, const float* __restrict__ w3,
    const int* __restrict__ ci, float* __restrict__ out)
{
    __shared__ __align__(16) float S[8 * PLANE];   // sigmoided channels + halo
    __shared__ __align__(16) float Wc[26 * 16];    // Möbius coeffs

    const int o   = blockIdx.x;          // 0..31
    const int b   = blockIdx.y;          // 0..7
    const int h0  = blockIdx.z << 3;     // 0,8,16,24
    const int tid = threadIdx.x;

    // ---- Stage + Möbius-transform weights (thread t handles LUT t) ----
    if (tid < 26) {
        const float* src;
        if (tid < 18)      src = w0 + o * 288 + tid * 16;
        else if (tid < 23) src = w1 + o * 80  + (tid - 18) * 16;
        else if (tid < 25) src = w2 + o * 32  + (tid - 23) * 16;
        else               src = w3 + o * 16;
        float t16[16];
        #pragma unroll
        for (int i = 0; i < 16; i++) t16[i] = src[i];
        #pragma unroll
        for (int d = 0; d < 4; d++) {       // finite-difference along each dim
            const int s = 1 << d;
            #pragma unroll
            for (int j = 0; j < 16; j++)
                if (j & s) t16[j] -= t16[j ^ s];
        }
        #pragma unroll
        for (int i = 0; i < 16; i++) Wc[tid * 16 + i] = t16[i];
    }

    // ---- Init planes to sigmoid(0)=0.5 (covers conv zero-pad halo) ----
    {
        float4 hv = make_float4(0.5f, 0.5f, 0.5f, 0.5f);
        float4* S4 = reinterpret_cast<float4*>(S);
        for (int i = tid; i < 8 * PLANE / 4; i += 128) S4[i] = hv;
    }
    __syncthreads();

    // ---- Fill interior: sigmoid of selected channels for this h-quarter ----
    #pragma unroll
    for (int q = 0; q < 8; q++) {
        const int ch = ci[o * 8 + q];
        const float* xc = x + ((size_t)(b * 64 + ch)) * 1024;
        for (int i = tid; i < HROWS * 32; i += 128) {
            const int r = i >> 5, w = i & 31;
            const int hin = h0 - 1 + r;
            if (hin >= 0 && hin < 32)
                S[q * PLANE + r * STRIDE + 1 + w] = fsig(xc[hin * 32 + w]);
        }
    }
    __syncthreads();

    // ---- Eval: thread -> output row ty (of 8), 2 consecutive cols ----
    const int ty = tid >> 4;              // 0..7
    const int wb = (tid & 15) << 1;       // 0..30 (even -> 8B aligned)
    const int base = ty * STRIDE + wb;

    float h1s[2][5];   // sigmoided level-1 outputs per pixel

    #pragma unroll
    for (int g = 0; g < 5; g++) {
        float in[4][2];                   // [level1 input k][pixel]
        #pragma unroll
        for (int k = 0; k < 4; k++) {
            const int l = g * 4 + k;
            if (l < 18) {
                float c[16]; ldc16(c, Wc, l);
                // features j=4l..4l+3 span exactly 2 feature-rows rA, rA+1
                const int rA = (4 * l) / 3;
                const int rB = rA + 1;
                float va[4], vb[4];
                {
                    const float* pa = S + (rA / 3) * PLANE + (ty + rA % 3) * STRIDE + wb;
                    float2 f0 = *(const float2*)pa;
                    float2 f1 = *(const float2*)(pa + 2);
                    va[0] = f0.x; va[1] = f0.y; va[2] = f1.x; va[3] = f1.y;
                }
                {
                    const float* pb = S + (rB / 3) * PLANE + (ty + rB % 3) * STRIDE + wb;
                    float2 f0 = *(const float2*)pb;
                    float2 f1 = *(const float2*)(pb + 2);
                    vb[0] = f0.x; vb[1] = f0.y; vb[2] = f1.x; vb[3] = f1.y;
                }
                #pragma unroll
                for (int p = 0; p < 2; p++) {
                    float xi[4];
                    #pragma unroll
                    for (int i = 0; i < 4; i++) {
                        const int j  = 4 * l + i;        // compile-time
                        const int rr = j / 3;
                        const int kw = j % 3;
                        xi[i] = (rr == rA) ? va[kw + p] : vb[kw + p];
                    }
                    in[k][p] = fsig(lut4m(c, xi[0], xi[1], xi[2], xi[3]));
                }
            } else {
                in[k][0] = 0.5f; in[k][1] = 0.5f;   // post-sigmoid pad
            }
        }
        float c[16]; ldc16(c, Wc, 18 + g);
        #pragma unroll
        for (int p = 0; p < 2; p++)
            h1s[p][g] = fsig(lut4m(c, in[0][p], in[1][p], in[2][p], in[3][p]));
    }

    // Level 2: LUT0 <- h1[0..3]; LUT1 <- h1[4], pad, pad, pad.
    float h2s[2][2];
    {
        float c[16]; ldc16(c, Wc, 23);
        #pragma unroll
        for (int p = 0; p < 2; p++)
            h2s[p][0] = fsig(lut4m(c, h1s[p][0], h1s[p][1], h1s[p][2], h1s[p][3]));
    }
    {
        float c[16]; ldc16(c, Wc, 24);
        #pragma unroll
        for (int p = 0; p < 2; p++)
            h2s[p][1] = fsig(lut4m(c, h1s[p][4], 0.5f, 0.5f, 0.5f));
    }

    // Level 3 (no sigmoid): inputs h2[0], h2[1], pad, pad.
    float2 ov;
    {
        float c[16]; ldc16(c, Wc, 25);
        ov.x = lut4m(c, h2s[0][0], h2s[0][1], 0.5f, 0.5f);
        ov.y = lut4m(c, h2s[1][0], h2s[1][1], 0.5f, 0.5f);
    }

    const int h = h0 + ty;
    *reinterpret_cast<float2*>(&out[(((b * 32 + o) * 32 + h) * 32) + wb]) = ov;
}

extern "C" void kernel_launch(void* const* d_in, const int* in_sizes, int n_in,
                              void* d_out, int out_size) {
    const float* x  = (const float*)d_in[0];
    const float* w0 = (const float*)d_in[1];
    const float* w1 = (const float*)d_in[2];
    const float* w2 = (const float*)d_in[3];
    const float* w3 = (const float*)d_in[4];
    const int*   ci = (const int*)d_in[5];
    dim3 grid(32, 8, 4);   // (O, B, H-quarter)
    lut_tree_kernel<<<grid, 128>>>(x, w0, w1, w2, w3, ci, (float*)d_out);
}